// round 5
// baseline (speedup 1.0000x reference)
#include <cuda_runtime.h>
#include <cstdint>

// Problem constants
#define NROWS 65536          // N = 4096*16
#define TTRAJ 8
// Output layout (floats), concatenated: traj, mu, logvar, prob_list
#define TRAJ_T_STRIDE 4194304ull   // 16*65536*4
#define TRAJ_H_STRIDE 262144ull    // 65536*4
#define MU_OFF   33554432ull
#define LV_OFF   35651584ull
#define PROB_OFF 37748736ull

// scratch: per-row mu[32] then std[32]
static __device__ __align__(16) float g_musig[NROWS * 64];
// transpose scratch for all weights
static __device__ __align__(16) float g_xpose[13440];

// constant weights (floats):
//   [0]     d2w^T [h][o]  60x64  (3840)
//   [3840]  mw^T  [h][m]  60x32  (1920)
//   [5760]  sw^T  [h][m]  60x32  (1920)
//   [7680]  d1w^T [l][h]  32x60  (1920)
//   [9600]  e1w^T [l][h]  64x60  (3840)
__constant__ __align__(16) float c_w[13440];

#define CW_D2 0
#define CW_MW 3840
#define CW_SW 5760
#define CW_D1 7680
#define CW_E1 9600

// ---------------- packed f32x2 helpers ----------------
__device__ __forceinline__ unsigned long long pk2(float a, float b) {
    unsigned long long r;
    asm("mov.b64 %0, {%1, %2};" : "=l"(r) : "f"(a), "f"(b));
    return r;
}
__device__ __forceinline__ float2 upk(unsigned long long v) {
    float2 r;
    asm("mov.b64 {%0, %1}, %2;" : "=f"(r.x), "=f"(r.y) : "l"(v));
    return r;
}
__device__ __forceinline__ unsigned long long ffma2(unsigned long long a,
                                                    unsigned long long b,
                                                    unsigned long long c) {
    unsigned long long d;
    asm("fma.rn.f32x2 %0, %1, %2, %3;" : "=l"(d) : "l"(a), "l"(b), "l"(c));
    return d;
}

// ---------------- JAX threefry2x32, key = (0,1) ----------------
__device__ __forceinline__ uint32_t rotl32(uint32_t x, int r) {
    return __funnelshift_l(x, x, r);
}
__device__ __forceinline__ uint32_t tf_bits(uint32_t c) {
    const uint32_t ks2 = 0x1BD11BDBu;
    uint32_t x0 = 0u;
    uint32_t x1 = c + 1u;
    x0 += x1; x1 = rotl32(x1, 13); x1 ^= x0;
    x0 += x1; x1 = rotl32(x1, 15); x1 ^= x0;
    x0 += x1; x1 = rotl32(x1, 26); x1 ^= x0;
    x0 += x1; x1 = rotl32(x1, 6);  x1 ^= x0;
    x0 += 1u;            x1 += ks2 + 1u;
    x0 += x1; x1 = rotl32(x1, 17); x1 ^= x0;
    x0 += x1; x1 = rotl32(x1, 29); x1 ^= x0;
    x0 += x1; x1 = rotl32(x1, 16); x1 ^= x0;
    x0 += x1; x1 = rotl32(x1, 24); x1 ^= x0;
    x0 += ks2;           x1 += 2u;
    x0 += x1; x1 = rotl32(x1, 13); x1 ^= x0;
    x0 += x1; x1 = rotl32(x1, 15); x1 ^= x0;
    x0 += x1; x1 = rotl32(x1, 26); x1 ^= x0;
    x0 += x1; x1 = rotl32(x1, 6);  x1 ^= x0;
    x0 += 0u;            x1 += 1u + 3u;
    x0 += x1; x1 = rotl32(x1, 17); x1 ^= x0;
    x0 += x1; x1 = rotl32(x1, 29); x1 ^= x0;
    x0 += x1; x1 = rotl32(x1, 16); x1 ^= x0;
    x0 += x1; x1 = rotl32(x1, 24); x1 ^= x0;
    x0 += 1u;            x1 += ks2 + 4u;
    x0 += x1; x1 = rotl32(x1, 13); x1 ^= x0;
    x0 += x1; x1 = rotl32(x1, 15); x1 ^= x0;
    x0 += x1; x1 = rotl32(x1, 26); x1 ^= x0;
    x0 += x1; x1 = rotl32(x1, 6);  x1 ^= x0;
    x0 += ks2;           x1 += 5u;
    return x0 ^ x1;
}

// Branchless XLA ErfInv f32 with fast log
__device__ __forceinline__ float bits_to_normal(uint32_t b) {
    const float U_LO = -0.99999994f;
    float f = __uint_as_float((b >> 9) | 0x3f800000u) - 1.0f;
    float u = f * 2.0f + U_LO;
    u = fmaxf(u, U_LO);

    float w = -__logf(fmaf(-u, u, 1.0f));
    float wf = w - 2.5f;
    float pf = 2.81022636e-08f;
    pf = fmaf(pf, wf, 3.43273939e-07f);
    pf = fmaf(pf, wf, -3.5233877e-06f);
    pf = fmaf(pf, wf, -4.39150654e-06f);
    pf = fmaf(pf, wf, 0.00021858087f);
    pf = fmaf(pf, wf, -0.00125372503f);
    pf = fmaf(pf, wf, -0.00417768164f);
    pf = fmaf(pf, wf, 0.246640727f);
    pf = fmaf(pf, wf, 1.50140941f);
    float ws = __fsqrt_rn(w) - 3.0f;
    float ps = -0.000200214257f;
    ps = fmaf(ps, ws, 0.000100950558f);
    ps = fmaf(ps, ws, 0.00134934322f);
    ps = fmaf(ps, ws, -0.00367342844f);
    ps = fmaf(ps, ws, 0.00573950773f);
    ps = fmaf(ps, ws, -0.0076224613f);
    ps = fmaf(ps, ws, 0.00943887047f);
    ps = fmaf(ps, ws, 1.00167406f);
    ps = fmaf(ps, ws, 2.83297682f);

    float p = (w < 5.0f) ? pf : ps;
    return 1.41421356237f * p * u;
}

// ======================= prep: transpose weights for constant bank =========
__global__ void prep_kernel(const float* __restrict__ d2w,
                            const float* __restrict__ mw,
                            const float* __restrict__ sw,
                            const float* __restrict__ d1w,
                            const float* __restrict__ e1w)
{
    int tid = blockIdx.x * 256 + threadIdx.x;
    // d2w [64][60] -> [h][o] 60x64
    for (int idx = tid; idx < 3840; idx += 512) {
        int h = idx >> 6, o = idx & 63;
        g_xpose[CW_D2 + idx] = d2w[o * 60 + h];
    }
    // mw, sw [32][60] -> [h][m] 60x32
    for (int idx = tid; idx < 1920; idx += 512) {
        int h = idx >> 5, m = idx & 31;
        g_xpose[CW_MW + idx] = mw[m * 60 + h];
        g_xpose[CW_SW + idx] = sw[m * 60 + h];
    }
    // d1w [60][32] -> [l][h] 32x60
    for (int idx = tid; idx < 1920; idx += 512) {
        int l = idx / 60, h = idx - l * 60;
        g_xpose[CW_D1 + idx] = d1w[h * 32 + l];
    }
    // e1w [60][64] -> [l][h] 64x60
    for (int idx = tid; idx < 3840; idx += 512) {
        int l = idx / 60, h = idx - l * 60;
        g_xpose[CW_E1 + idx] = e1w[h * 64 + l];
    }
}

// ======================= encoder =======================
// one thread per row n: x[64] -> h1[60] -> mu[32], logvar[32]
// all weights via constant port
__global__ __launch_bounds__(256, 2) void enc_kernel(
    const float* __restrict__ x_in,
    const float* __restrict__ e1b,
    const float* __restrict__ mb,  const float* __restrict__ sb,
    float* __restrict__ out)
{
    __shared__ __align__(16) float e1bs[60];
    __shared__ __align__(16) float mbs[32];
    __shared__ __align__(16) float sbs[32];

    int tid = threadIdx.x;
    if (tid < 60) e1bs[tid] = e1b[tid];
    if (tid < 32) { mbs[tid] = mb[tid]; sbs[tid] = sb[tid]; }
    __syncthreads();

    int n = blockIdx.x * 256 + tid;

    unsigned long long h1a[30];
#pragma unroll
    for (int j = 0; j < 30; j++) {
        float2 b2 = *(const float2*)&e1bs[2 * j];
        h1a[j] = pk2(b2.x, b2.y);
    }
    const float4* xr = (const float4*)(x_in + (size_t)n * 64);
#pragma unroll
    for (int q = 0; q < 16; q++) {
        float4 xv = xr[q];
        float xs[4] = {xv.x, xv.y, xv.z, xv.w};
#pragma unroll
        for (int s = 0; s < 4; s++) {
            unsigned long long xb = pk2(xs[s], xs[s]);
            const ulonglong2* wr =
                (const ulonglong2*)&c_w[CW_E1 + (q * 4 + s) * 60];
#pragma unroll
            for (int j = 0; j < 15; j++) {
                ulonglong2 wv = wr[j];
                h1a[2 * j]     = ffma2(wv.x, xb, h1a[2 * j]);
                h1a[2 * j + 1] = ffma2(wv.y, xb, h1a[2 * j + 1]);
            }
        }
    }
    float h1f[60];
#pragma unroll
    for (int j = 0; j < 30; j++) {
        float2 v = upk(h1a[j]);
        h1f[2 * j]     = fmaxf(v.x, 0.0f);
        h1f[2 * j + 1] = fmaxf(v.y, 0.0f);
    }

    float2* gm = (float2*)(g_musig + (size_t)n * 64);

    // ---- pass 1: mu ----
    {
        unsigned long long mua[16];
#pragma unroll
        for (int j = 0; j < 16; j++) {
            float2 b2 = *(const float2*)&mbs[2 * j];
            mua[j] = pk2(b2.x, b2.y);
        }
#pragma unroll
        for (int h = 0; h < 60; h++) {
            unsigned long long hb = pk2(h1f[h], h1f[h]);
            const ulonglong2* mr = (const ulonglong2*)&c_w[CW_MW + h * 32];
#pragma unroll
            for (int j = 0; j < 8; j++) {
                ulonglong2 mv = mr[j];
                mua[2 * j]     = ffma2(mv.x, hb, mua[2 * j]);
                mua[2 * j + 1] = ffma2(mv.y, hb, mua[2 * j + 1]);
            }
        }
        float2* mo = (float2*)(out + MU_OFF) + (size_t)n * 16;
#pragma unroll
        for (int j = 0; j < 16; j++) {
            float2 m = upk(mua[j]);
            mo[j] = m;
            gm[j] = m;
        }
    }

    // ---- pass 2: logvar ----
    {
        unsigned long long lva[16];
#pragma unroll
        for (int j = 0; j < 16; j++) {
            float2 c2 = *(const float2*)&sbs[2 * j];
            lva[j] = pk2(c2.x, c2.y);
        }
#pragma unroll
        for (int h = 0; h < 60; h++) {
            unsigned long long hb = pk2(h1f[h], h1f[h]);
            const ulonglong2* sr = (const ulonglong2*)&c_w[CW_SW + h * 32];
#pragma unroll
            for (int j = 0; j < 8; j++) {
                ulonglong2 sv = sr[j];
                lva[2 * j]     = ffma2(sv.x, hb, lva[2 * j]);
                lva[2 * j + 1] = ffma2(sv.y, hb, lva[2 * j + 1]);
            }
        }
        float2* vo = (float2*)(out + LV_OFF) + (size_t)n * 16;
#pragma unroll
        for (int j = 0; j < 16; j++) {
            float2 v = upk(lva[j]);
            vo[j] = v;
            gm[16 + j] = make_float2(expf(0.5f * v.x), expf(0.5f * v.y));
        }
    }
}

// ======================= decoder =======================
// one thread per (n, t): eps[32] -> z[32] -> h3[60] -> out[64] (two halves)
// all weights via constant port; LSU carries only global traffic
__global__ __launch_bounds__(256, 2) void dec_kernel(
    const float* __restrict__ d1b,
    const float* __restrict__ d2b,
    float* __restrict__ out)
{
    __shared__ __align__(16) float d1bs[60];
    __shared__ __align__(16) float d2bs[64];

    int tid = threadIdx.x;
    if (tid < 60) d1bs[tid] = d1b[tid];
    if (tid < 64) d2bs[tid] = d2b[tid];
    __syncthreads();

    unsigned g = blockIdx.x * 256 + tid;
    int n = g & (NROWS - 1);
    int t = g >> 16;

    float h3f[60];
    {
        // ---- eps -> z ----
        float z[32];
        uint32_t c0 = ((uint32_t)t << 21) | ((uint32_t)n << 5);
        const float4* m4 = (const float4*)(g_musig + (size_t)n * 64);
#pragma unroll
        for (int q = 0; q < 8; q++) {
            float4 mu = m4[q];
            float4 sd = m4[8 + q];
            float mus[4] = {mu.x, mu.y, mu.z, mu.w};
            float sds[4] = {sd.x, sd.y, sd.z, sd.w};
#pragma unroll
            for (int s = 0; s < 4; s++) {
                int l = q * 4 + s;
                float e = bits_to_normal(tf_bits(c0 + (uint32_t)l));
                z[l] = fmaf(e, sds[s], mus[s]);   // mu + eps*std
            }
        }

        // ---- h3 = relu(dec1_w @ z + b), weights via const port ----
        unsigned long long h3a[30];
#pragma unroll
        for (int j = 0; j < 30; j++) {
            float2 b2 = *(const float2*)&d1bs[2 * j];
            h3a[j] = pk2(b2.x, b2.y);
        }
#pragma unroll
        for (int l = 0; l < 32; l++) {
            unsigned long long zb = pk2(z[l], z[l]);
            const ulonglong2* wr = (const ulonglong2*)&c_w[CW_D1 + l * 60];
#pragma unroll
            for (int j = 0; j < 15; j++) {
                ulonglong2 wv = wr[j];
                h3a[2 * j]     = ffma2(wv.x, zb, h3a[2 * j]);
                h3a[2 * j + 1] = ffma2(wv.y, zb, h3a[2 * j + 1]);
            }
        }
#pragma unroll
        for (int j = 0; j < 30; j++) {
            float2 v = upk(h3a[j]);
            h3f[2 * j]     = fmaxf(v.x, 0.0f);
            h3f[2 * j + 1] = fmaxf(v.y, 0.0f);
        }
    }   // z, h3a dead here

    // ---- o = dec2_w @ h3 + b, weights via const port, two halves ----
    float* tb = out + (size_t)t * TRAJ_T_STRIDE + (size_t)n * 4;
#pragma unroll
    for (int half = 0; half < 2; half++) {
        unsigned long long oa[16];
#pragma unroll
        for (int j = 0; j < 16; j++) {
            float2 b2 = *(const float2*)&d2bs[half * 32 + 2 * j];
            oa[j] = pk2(b2.x, b2.y);
        }
#pragma unroll
        for (int h = 0; h < 60; h++) {
            unsigned long long hb = pk2(h3f[h], h3f[h]);
            const ulonglong2* wr =
                (const ulonglong2*)&c_w[CW_D2 + h * 64 + half * 32];
#pragma unroll
            for (int j = 0; j < 8; j++) {
                ulonglong2 wv = wr[j];
                oa[2 * j]     = ffma2(wv.x, hb, oa[2 * j]);
                oa[2 * j + 1] = ffma2(wv.y, hb, oa[2 * j + 1]);
            }
        }
#pragma unroll
        for (int jj = 0; jj < 8; jj++) {
            int hi = half * 8 + jj;
            float2 a  = upk(oa[2 * jj]);
            float2 b2 = upk(oa[2 * jj + 1]);
            *(float4*)(tb + (size_t)hi * TRAJ_H_STRIDE) =
                make_float4(a.x, a.y, b2.x, b2.y);
        }
    }

    // prob_list: exp(pdf)==1.0f exactly in fp32, so 1/8.
    out[PROB_OFF + ((size_t)t << 16) + (size_t)n] = 0.125f;
}

extern "C" void kernel_launch(void* const* d_in, const int* in_sizes, int n_in,
                              void* d_out, int out_size) {
    (void)in_sizes; (void)n_in; (void)out_size;
    const float* h_input = (const float*)d_in[0];
    const float* e1w = (const float*)d_in[2];
    const float* e1b = (const float*)d_in[3];
    const float* mw  = (const float*)d_in[4];
    const float* mb  = (const float*)d_in[5];
    const float* sw  = (const float*)d_in[6];
    const float* sb  = (const float*)d_in[7];
    const float* d1w = (const float*)d_in[8];
    const float* d1b = (const float*)d_in[9];
    const float* d2w = (const float*)d_in[10];
    const float* d2b = (const float*)d_in[11];
    float* out = (float*)d_out;

    // transpose weights on device, then D2D into constant bank (capturable)
    prep_kernel<<<2, 256>>>(d2w, mw, sw, d1w, e1w);
    void* xp_ptr = nullptr;
    cudaGetSymbolAddress(&xp_ptr, g_xpose);
    cudaMemcpyToSymbolAsync(c_w, xp_ptr, 13440 * sizeof(float), 0,
                            cudaMemcpyDeviceToDevice, 0);

    enc_kernel<<<NROWS / 256, 256>>>(h_input, e1b, mb, sb, out);
    dec_kernel<<<(NROWS * TTRAJ) / 256, 256>>>(d1b, d2b, out);
}

// round 6
// speedup vs baseline: 1.0125x; 1.0125x over previous
#include <cuda_runtime.h>
#include <cstdint>

// Problem constants
#define NROWS 65536          // N = 4096*16
#define TTRAJ 8
// Output layout (floats), concatenated: traj, mu, logvar, prob_list
#define TRAJ_T_STRIDE 4194304ull   // 16*65536*4
#define TRAJ_H_STRIDE 262144ull    // 65536*4
#define MU_OFF   33554432ull
#define LV_OFF   35651584ull
#define PROB_OFF 37748736ull

// scratch: per-row mu[32] then std[32]
static __device__ __align__(16) float g_musig[NROWS * 64];
// transpose scratch for all weights + biases
static __device__ __align__(16) float g_xpose[13696];

// constant weights (floats):
//   [0]     d2w^T [h][o]  60x64  (3840)
//   [3840]  mw^T  [h][m]  60x32  (1920)
//   [5760]  sw^T  [h][m]  60x32  (1920)
//   [7680]  d1w^T [l][h]  32x60  (1920)
//   [9600]  e1w^T [l][h]  64x60  (3840)
//   [13440] d1b (60), [13500] d2b (64), [13564] e1b (60),
//   [13624] mb (32), [13656] sb (32)
__constant__ __align__(16) float c_w[13696];

#define CW_D2  0
#define CW_MW  3840
#define CW_SW  5760
#define CW_D1  7680
#define CW_E1  9600
#define CW_B1  13440
#define CW_B2  13500
#define CW_BE1 13564
#define CW_BM  13624
#define CW_BS  13656

// ---------------- packed f32x2 helpers ----------------
__device__ __forceinline__ unsigned long long pk2(float a, float b) {
    unsigned long long r;
    asm("mov.b64 %0, {%1, %2};" : "=l"(r) : "f"(a), "f"(b));
    return r;
}
__device__ __forceinline__ float2 upk(unsigned long long v) {
    float2 r;
    asm("mov.b64 {%0, %1}, %2;" : "=f"(r.x), "=f"(r.y) : "l"(v));
    return r;
}
__device__ __forceinline__ unsigned long long ffma2(unsigned long long a,
                                                    unsigned long long b,
                                                    unsigned long long c) {
    unsigned long long d;
    asm("fma.rn.f32x2 %0, %1, %2, %3;" : "=l"(d) : "l"(a), "l"(b), "l"(c));
    return d;
}

// ---------------- JAX threefry2x32, key = (0,1) ----------------
__device__ __forceinline__ uint32_t rotl32(uint32_t x, int r) {
    return __funnelshift_l(x, x, r);
}
__device__ __forceinline__ uint32_t tf_bits(uint32_t c) {
    const uint32_t ks2 = 0x1BD11BDBu;
    uint32_t x0 = 0u;
    uint32_t x1 = c + 1u;
    x0 += x1; x1 = rotl32(x1, 13); x1 ^= x0;
    x0 += x1; x1 = rotl32(x1, 15); x1 ^= x0;
    x0 += x1; x1 = rotl32(x1, 26); x1 ^= x0;
    x0 += x1; x1 = rotl32(x1, 6);  x1 ^= x0;
    x0 += 1u;            x1 += ks2 + 1u;
    x0 += x1; x1 = rotl32(x1, 17); x1 ^= x0;
    x0 += x1; x1 = rotl32(x1, 29); x1 ^= x0;
    x0 += x1; x1 = rotl32(x1, 16); x1 ^= x0;
    x0 += x1; x1 = rotl32(x1, 24); x1 ^= x0;
    x0 += ks2;           x1 += 2u;
    x0 += x1; x1 = rotl32(x1, 13); x1 ^= x0;
    x0 += x1; x1 = rotl32(x1, 15); x1 ^= x0;
    x0 += x1; x1 = rotl32(x1, 26); x1 ^= x0;
    x0 += x1; x1 = rotl32(x1, 6);  x1 ^= x0;
    x0 += 0u;            x1 += 1u + 3u;
    x0 += x1; x1 = rotl32(x1, 17); x1 ^= x0;
    x0 += x1; x1 = rotl32(x1, 29); x1 ^= x0;
    x0 += x1; x1 = rotl32(x1, 16); x1 ^= x0;
    x0 += x1; x1 = rotl32(x1, 24); x1 ^= x0;
    x0 += 1u;            x1 += ks2 + 4u;
    x0 += x1; x1 = rotl32(x1, 13); x1 ^= x0;
    x0 += x1; x1 = rotl32(x1, 15); x1 ^= x0;
    x0 += x1; x1 = rotl32(x1, 26); x1 ^= x0;
    x0 += x1; x1 = rotl32(x1, 6);  x1 ^= x0;
    x0 += ks2;           x1 += 5u;
    return x0 ^ x1;
}

// Branchless XLA ErfInv f32 with fast log
__device__ __forceinline__ float bits_to_normal(uint32_t b) {
    const float U_LO = -0.99999994f;
    float f = __uint_as_float((b >> 9) | 0x3f800000u) - 1.0f;
    float u = f * 2.0f + U_LO;
    u = fmaxf(u, U_LO);

    float w = -__logf(fmaf(-u, u, 1.0f));
    float wf = w - 2.5f;
    float pf = 2.81022636e-08f;
    pf = fmaf(pf, wf, 3.43273939e-07f);
    pf = fmaf(pf, wf, -3.5233877e-06f);
    pf = fmaf(pf, wf, -4.39150654e-06f);
    pf = fmaf(pf, wf, 0.00021858087f);
    pf = fmaf(pf, wf, -0.00125372503f);
    pf = fmaf(pf, wf, -0.00417768164f);
    pf = fmaf(pf, wf, 0.246640727f);
    pf = fmaf(pf, wf, 1.50140941f);
    float ws = __fsqrt_rn(w) - 3.0f;
    float ps = -0.000200214257f;
    ps = fmaf(ps, ws, 0.000100950558f);
    ps = fmaf(ps, ws, 0.00134934322f);
    ps = fmaf(ps, ws, -0.00367342844f);
    ps = fmaf(ps, ws, 0.00573950773f);
    ps = fmaf(ps, ws, -0.0076224613f);
    ps = fmaf(ps, ws, 0.00943887047f);
    ps = fmaf(ps, ws, 1.00167406f);
    ps = fmaf(ps, ws, 2.83297682f);

    float p = (w < 5.0f) ? pf : ps;
    return 1.41421356237f * p * u;
}

// ======================= prep: transpose weights for constant bank =========
__global__ void prep_kernel(const float* __restrict__ d2w,
                            const float* __restrict__ mw,
                            const float* __restrict__ sw,
                            const float* __restrict__ d1w,
                            const float* __restrict__ e1w,
                            const float* __restrict__ d1b,
                            const float* __restrict__ d2b,
                            const float* __restrict__ e1b,
                            const float* __restrict__ mb,
                            const float* __restrict__ sb)
{
    int tid = blockIdx.x * 256 + threadIdx.x;
    // d2w [64][60] -> [h][o] 60x64
    for (int idx = tid; idx < 3840; idx += 512) {
        int h = idx >> 6, o = idx & 63;
        g_xpose[CW_D2 + idx] = d2w[o * 60 + h];
    }
    // mw, sw [32][60] -> [h][m] 60x32
    for (int idx = tid; idx < 1920; idx += 512) {
        int h = idx >> 5, m = idx & 31;
        g_xpose[CW_MW + idx] = mw[m * 60 + h];
        g_xpose[CW_SW + idx] = sw[m * 60 + h];
    }
    // d1w [60][32] -> [l][h] 32x60
    for (int idx = tid; idx < 1920; idx += 512) {
        int l = idx / 60, h = idx - l * 60;
        g_xpose[CW_D1 + idx] = d1w[h * 32 + l];
    }
    // e1w [60][64] -> [l][h] 64x60
    for (int idx = tid; idx < 3840; idx += 512) {
        int l = idx / 60, h = idx - l * 60;
        g_xpose[CW_E1 + idx] = e1w[h * 64 + l];
    }
    // biases
    if (tid < 60) g_xpose[CW_B1 + tid] = d1b[tid];
    if (tid < 64) g_xpose[CW_B2 + tid] = d2b[tid];
    if (tid < 60) g_xpose[CW_BE1 + tid] = e1b[tid];
    if (tid < 32) { g_xpose[CW_BM + tid] = mb[tid]; g_xpose[CW_BS + tid] = sb[tid]; }
}

// ======================= encoder =======================
// one thread per row n: x[64] -> h1[60] -> mu[32], logvar[32]
// all weights + biases via constant port; no smem, no barriers
__global__ __launch_bounds__(256, 2) void enc_kernel(
    const float* __restrict__ x_in,
    float* __restrict__ out)
{
    int tid = threadIdx.x;
    int n = blockIdx.x * 256 + tid;

    unsigned long long h1a[30];
    {
        const ulonglong2* bb = (const ulonglong2*)&c_w[CW_BE1];
#pragma unroll
        for (int j = 0; j < 15; j++) {
            ulonglong2 bv = bb[j];
            h1a[2 * j] = bv.x;
            h1a[2 * j + 1] = bv.y;
        }
    }
    const float4* xr = (const float4*)(x_in + (size_t)n * 64);
#pragma unroll
    for (int q = 0; q < 16; q++) {
        float4 xv = xr[q];
        float xs[4] = {xv.x, xv.y, xv.z, xv.w};
#pragma unroll
        for (int s = 0; s < 4; s++) {
            unsigned long long xb = pk2(xs[s], xs[s]);
            const ulonglong2* wr =
                (const ulonglong2*)&c_w[CW_E1 + (q * 4 + s) * 60];
#pragma unroll
            for (int j = 0; j < 15; j++) {
                ulonglong2 wv = wr[j];
                h1a[2 * j]     = ffma2(wv.x, xb, h1a[2 * j]);
                h1a[2 * j + 1] = ffma2(wv.y, xb, h1a[2 * j + 1]);
            }
        }
    }
    float h1f[60];
#pragma unroll
    for (int j = 0; j < 30; j++) {
        float2 v = upk(h1a[j]);
        h1f[2 * j]     = fmaxf(v.x, 0.0f);
        h1f[2 * j + 1] = fmaxf(v.y, 0.0f);
    }

    float2* gm = (float2*)(g_musig + (size_t)n * 64);

    // ---- pass 1: mu ----
    {
        unsigned long long mua[16];
        const ulonglong2* bb = (const ulonglong2*)&c_w[CW_BM];
#pragma unroll
        for (int j = 0; j < 8; j++) {
            ulonglong2 bv = bb[j];
            mua[2 * j] = bv.x;
            mua[2 * j + 1] = bv.y;
        }
#pragma unroll
        for (int h = 0; h < 60; h++) {
            unsigned long long hb = pk2(h1f[h], h1f[h]);
            const ulonglong2* mr = (const ulonglong2*)&c_w[CW_MW + h * 32];
#pragma unroll
            for (int j = 0; j < 8; j++) {
                ulonglong2 mv = mr[j];
                mua[2 * j]     = ffma2(mv.x, hb, mua[2 * j]);
                mua[2 * j + 1] = ffma2(mv.y, hb, mua[2 * j + 1]);
            }
        }
        float2* mo = (float2*)(out + MU_OFF) + (size_t)n * 16;
#pragma unroll
        for (int j = 0; j < 16; j++) {
            float2 m = upk(mua[j]);
            mo[j] = m;
            gm[j] = m;
        }
    }

    // ---- pass 2: logvar ----
    {
        unsigned long long lva[16];
        const ulonglong2* bb = (const ulonglong2*)&c_w[CW_BS];
#pragma unroll
        for (int j = 0; j < 8; j++) {
            ulonglong2 bv = bb[j];
            lva[2 * j] = bv.x;
            lva[2 * j + 1] = bv.y;
        }
#pragma unroll
        for (int h = 0; h < 60; h++) {
            unsigned long long hb = pk2(h1f[h], h1f[h]);
            const ulonglong2* sr = (const ulonglong2*)&c_w[CW_SW + h * 32];
#pragma unroll
            for (int j = 0; j < 8; j++) {
                ulonglong2 sv = sr[j];
                lva[2 * j]     = ffma2(sv.x, hb, lva[2 * j]);
                lva[2 * j + 1] = ffma2(sv.y, hb, lva[2 * j + 1]);
            }
        }
        float2* vo = (float2*)(out + LV_OFF) + (size_t)n * 16;
#pragma unroll
        for (int j = 0; j < 16; j++) {
            float2 v = upk(lva[j]);
            vo[j] = v;
            gm[16 + j] = make_float2(expf(0.5f * v.x), expf(0.5f * v.y));
        }
    }
}

// ======================= decoder =======================
// one thread per (n, t). RNG interleaved with dec1 accumulation (no z array);
// h3 parked in per-thread SMEM column (no barriers); dec2 single full pass.
__global__ __launch_bounds__(256, 3) void dec_kernel(float* __restrict__ out)
{
    extern __shared__ float h3s[];   // [60][256], per-thread column

    int tid = threadIdx.x;
    unsigned g = blockIdx.x * 256 + tid;
    int n = g & (NROWS - 1);
    int t = g >> 16;

    // ---- phase A: RNG -> z (on the fly) -> dec1 accumulate ----
    {
        unsigned long long h3a[30];
        const ulonglong2* bb = (const ulonglong2*)&c_w[CW_B1];
#pragma unroll
        for (int j = 0; j < 15; j++) {
            ulonglong2 bv = bb[j];
            h3a[2 * j] = bv.x;
            h3a[2 * j + 1] = bv.y;
        }

        uint32_t c0 = ((uint32_t)t << 21) | ((uint32_t)n << 5);
        const float4* m4 = (const float4*)(g_musig + (size_t)n * 64);
#pragma unroll
        for (int q = 0; q < 8; q++) {
            float4 mu = m4[q];
            float4 sd = m4[8 + q];
            float mus[4] = {mu.x, mu.y, mu.z, mu.w};
            float sds[4] = {sd.x, sd.y, sd.z, sd.w};
#pragma unroll
            for (int s = 0; s < 4; s++) {
                int l = q * 4 + s;
                float e = bits_to_normal(tf_bits(c0 + (uint32_t)l));
                float zv = fmaf(e, sds[s], mus[s]);   // mu + eps*std
                unsigned long long zb = pk2(zv, zv);
                const ulonglong2* wr = (const ulonglong2*)&c_w[CW_D1 + l * 60];
#pragma unroll
                for (int j = 0; j < 15; j++) {
                    ulonglong2 wv = wr[j];
                    h3a[2 * j]     = ffma2(wv.x, zb, h3a[2 * j]);
                    h3a[2 * j + 1] = ffma2(wv.y, zb, h3a[2 * j + 1]);
                }
            }
        }
        // relu -> smem (own column; no cross-thread sharing, no barrier)
#pragma unroll
        for (int j = 0; j < 30; j++) {
            float2 v = upk(h3a[j]);
            h3s[(2 * j) * 256 + tid]     = fmaxf(v.x, 0.0f);
            h3s[(2 * j + 1) * 256 + tid] = fmaxf(v.y, 0.0f);
        }
    }

    // ---- phase B: o = dec2_w @ h3 + b, full 64-wide accumulate ----
    {
        unsigned long long oa[32];
        const ulonglong2* bb = (const ulonglong2*)&c_w[CW_B2];
#pragma unroll
        for (int j = 0; j < 16; j++) {
            ulonglong2 bv = bb[j];
            oa[2 * j] = bv.x;
            oa[2 * j + 1] = bv.y;
        }
#pragma unroll
        for (int h = 0; h < 60; h++) {
            float hv = h3s[h * 256 + tid];
            unsigned long long hb = pk2(hv, hv);
            const ulonglong2* wr = (const ulonglong2*)&c_w[CW_D2 + h * 64];
#pragma unroll
            for (int j = 0; j < 16; j++) {
                ulonglong2 wv = wr[j];
                oa[2 * j]     = ffma2(wv.x, hb, oa[2 * j]);
                oa[2 * j + 1] = ffma2(wv.y, hb, oa[2 * j + 1]);
            }
        }
        float* tb = out + (size_t)t * TRAJ_T_STRIDE + (size_t)n * 4;
#pragma unroll
        for (int hi = 0; hi < 16; hi++) {
            float2 a  = upk(oa[2 * hi]);
            float2 b2 = upk(oa[2 * hi + 1]);
            *(float4*)(tb + (size_t)hi * TRAJ_H_STRIDE) =
                make_float4(a.x, a.y, b2.x, b2.y);
        }
    }

    // prob_list: exp(pdf)==1.0f exactly in fp32, so 1/8.
    out[PROB_OFF + ((size_t)t << 16) + (size_t)n] = 0.125f;
}

extern "C" void kernel_launch(void* const* d_in, const int* in_sizes, int n_in,
                              void* d_out, int out_size) {
    (void)in_sizes; (void)n_in; (void)out_size;
    const float* h_input = (const float*)d_in[0];
    const float* e1w = (const float*)d_in[2];
    const float* e1b = (const float*)d_in[3];
    const float* mw  = (const float*)d_in[4];
    const float* mb  = (const float*)d_in[5];
    const float* sw  = (const float*)d_in[6];
    const float* sb  = (const float*)d_in[7];
    const float* d1w = (const float*)d_in[8];
    const float* d1b = (const float*)d_in[9];
    const float* d2w = (const float*)d_in[10];
    const float* d2b = (const float*)d_in[11];
    float* out = (float*)d_out;

    cudaFuncSetAttribute(dec_kernel,
                         cudaFuncAttributeMaxDynamicSharedMemorySize,
                         60 * 256 * 4);

    // transpose weights on device, then D2D into constant bank (capturable)
    prep_kernel<<<2, 256>>>(d2w, mw, sw, d1w, e1w, d1b, d2b, e1b, mb, sb);
    void* xp_ptr = nullptr;
    cudaGetSymbolAddress(&xp_ptr, g_xpose);
    cudaMemcpyToSymbolAsync(c_w, xp_ptr, 13696 * sizeof(float), 0,
                            cudaMemcpyDeviceToDevice, 0);

    enc_kernel<<<NROWS / 256, 256>>>(h_input, out);
    dec_kernel<<<(NROWS * TTRAJ) / 256, 256, 60 * 256 * 4>>>(out);
}

// round 7
// speedup vs baseline: 1.1131x; 1.0994x over previous
#include <cuda_runtime.h>
#include <cstdint>

// Problem constants
#define NROWS 65536          // N = 4096*16
#define TTRAJ 8
// Output layout (floats), concatenated: traj, mu, logvar, prob_list
#define TRAJ_T_STRIDE 4194304ull   // 16*65536*4
#define TRAJ_H_STRIDE 262144ull    // 65536*4
#define MU_OFF   33554432ull
#define LV_OFF   35651584ull
#define PROB_OFF 37748736ull

// scratch: per-row mu[32] then std[32]
static __device__ __align__(16) float g_musig[NROWS * 64];
// transpose scratch for all weights + biases
static __device__ __align__(16) float g_xpose[13696];

// constant weights (floats):
//   [0]     d2w^T [h][o]  60x64  (3840)
//   [3840]  mw^T  [h][m]  60x32  (1920)
//   [5760]  sw^T  [h][m]  60x32  (1920)
//   [7680]  d1w^T [l][h]  32x60  (1920)
//   [9600]  e1w^T [l][h]  64x60  (3840)
//   [13440] d1b (60), [13500] d2b (64), [13564] e1b (60),
//   [13624] mb (32), [13656] sb (32)
__constant__ __align__(16) float c_w[13696];

#define CW_D2  0
#define CW_MW  3840
#define CW_SW  5760
#define CW_D1  7680
#define CW_E1  9600
#define CW_B1  13440
#define CW_B2  13500
#define CW_BE1 13564
#define CW_BM  13624
#define CW_BS  13656

// ---------------- packed f32x2 helpers ----------------
__device__ __forceinline__ unsigned long long pk2(float a, float b) {
    unsigned long long r;
    asm("mov.b64 %0, {%1, %2};" : "=l"(r) : "f"(a), "f"(b));
    return r;
}
__device__ __forceinline__ float2 upk(unsigned long long v) {
    float2 r;
    asm("mov.b64 {%0, %1}, %2;" : "=f"(r.x), "=f"(r.y) : "l"(v));
    return r;
}
__device__ __forceinline__ unsigned long long ffma2(unsigned long long a,
                                                    unsigned long long b,
                                                    unsigned long long c) {
    unsigned long long d;
    asm("fma.rn.f32x2 %0, %1, %2, %3;" : "=l"(d) : "l"(a), "l"(b), "l"(c));
    return d;
}
__device__ __forceinline__ unsigned long long add2(unsigned long long a,
                                                   unsigned long long b) {
    unsigned long long d;
    asm("add.rn.f32x2 %0, %1, %2;" : "=l"(d) : "l"(a), "l"(b));
    return d;
}
__device__ __forceinline__ unsigned long long mul2(unsigned long long a,
                                                   unsigned long long b) {
    unsigned long long d;
    asm("mul.rn.f32x2 %0, %1, %2;" : "=l"(d) : "l"(a), "l"(b));
    return d;
}

// ---------------- JAX threefry2x32, key = (0,1) ----------------
__device__ __forceinline__ uint32_t rotl32(uint32_t x, int r) {
    return __funnelshift_l(x, x, r);
}
__device__ __forceinline__ uint32_t tf_bits(uint32_t c) {
    const uint32_t ks2 = 0x1BD11BDBu;
    uint32_t x0 = 0u;
    uint32_t x1 = c + 1u;
    x0 += x1; x1 = rotl32(x1, 13); x1 ^= x0;
    x0 += x1; x1 = rotl32(x1, 15); x1 ^= x0;
    x0 += x1; x1 = rotl32(x1, 26); x1 ^= x0;
    x0 += x1; x1 = rotl32(x1, 6);  x1 ^= x0;
    x0 += 1u;            x1 += ks2 + 1u;
    x0 += x1; x1 = rotl32(x1, 17); x1 ^= x0;
    x0 += x1; x1 = rotl32(x1, 29); x1 ^= x0;
    x0 += x1; x1 = rotl32(x1, 16); x1 ^= x0;
    x0 += x1; x1 = rotl32(x1, 24); x1 ^= x0;
    x0 += ks2;           x1 += 2u;
    x0 += x1; x1 = rotl32(x1, 13); x1 ^= x0;
    x0 += x1; x1 = rotl32(x1, 15); x1 ^= x0;
    x0 += x1; x1 = rotl32(x1, 26); x1 ^= x0;
    x0 += x1; x1 = rotl32(x1, 6);  x1 ^= x0;
    x0 += 0u;            x1 += 1u + 3u;
    x0 += x1; x1 = rotl32(x1, 17); x1 ^= x0;
    x0 += x1; x1 = rotl32(x1, 29); x1 ^= x0;
    x0 += x1; x1 = rotl32(x1, 16); x1 ^= x0;
    x0 += x1; x1 = rotl32(x1, 24); x1 ^= x0;
    x0 += 1u;            x1 += ks2 + 4u;
    x0 += x1; x1 = rotl32(x1, 13); x1 ^= x0;
    x0 += x1; x1 = rotl32(x1, 15); x1 ^= x0;
    x0 += x1; x1 = rotl32(x1, 26); x1 ^= x0;
    x0 += x1; x1 = rotl32(x1, 6);  x1 ^= x0;
    x0 += ks2;           x1 += 5u;
    return x0 ^ x1;
}

// Paired branchless XLA ErfInv: two samples per packed-f32x2 polynomial.
// Per-lane fma.rn is IEEE round-to-nearest -> bit-identical to scalar path.
__device__ __forceinline__ float2 bits_pair_to_normal(uint32_t b0, uint32_t b1) {
    const float U_LO = -0.99999994f;
    float u0 = fmaxf(__uint_as_float((b0 >> 9) | 0x3f800000u) - 1.0f, 0.0f);
    float u1 = fmaxf(__uint_as_float((b1 >> 9) | 0x3f800000u) - 1.0f, 0.0f);
    // note: f in [0,1) so fmax vs 0 is a no-op; real clamp below
    u0 = fmaxf(fmaf(u0, 2.0f, U_LO), U_LO);
    u1 = fmaxf(fmaf(u1, 2.0f, U_LO), U_LO);

    float w0 = -__logf(fmaf(-u0, u0, 1.0f));
    float w1 = -__logf(fmaf(-u1, u1, 1.0f));

    // fast arm, packed
    unsigned long long WF = pk2(w0 - 2.5f, w1 - 2.5f);
    unsigned long long P = pk2(2.81022636e-08f, 2.81022636e-08f);
    P = ffma2(P, WF, pk2(3.43273939e-07f, 3.43273939e-07f));
    P = ffma2(P, WF, pk2(-3.5233877e-06f, -3.5233877e-06f));
    P = ffma2(P, WF, pk2(-4.39150654e-06f, -4.39150654e-06f));
    P = ffma2(P, WF, pk2(0.00021858087f, 0.00021858087f));
    P = ffma2(P, WF, pk2(-0.00125372503f, -0.00125372503f));
    P = ffma2(P, WF, pk2(-0.00417768164f, -0.00417768164f));
    P = ffma2(P, WF, pk2(0.246640727f, 0.246640727f));
    P = ffma2(P, WF, pk2(1.50140941f, 1.50140941f));

    // slow arm, packed
    unsigned long long WS = pk2(__fsqrt_rn(w0) - 3.0f, __fsqrt_rn(w1) - 3.0f);
    unsigned long long Q = pk2(-0.000200214257f, -0.000200214257f);
    Q = ffma2(Q, WS, pk2(0.000100950558f, 0.000100950558f));
    Q = ffma2(Q, WS, pk2(0.00134934322f, 0.00134934322f));
    Q = ffma2(Q, WS, pk2(-0.00367342844f, -0.00367342844f));
    Q = ffma2(Q, WS, pk2(0.00573950773f, 0.00573950773f));
    Q = ffma2(Q, WS, pk2(-0.0076224613f, -0.0076224613f));
    Q = ffma2(Q, WS, pk2(0.00943887047f, 0.00943887047f));
    Q = ffma2(Q, WS, pk2(1.00167406f, 1.00167406f));
    Q = ffma2(Q, WS, pk2(2.83297682f, 2.83297682f));

    float2 pf = upk(P), ps = upk(Q);
    float p0 = (w0 < 5.0f) ? pf.x : ps.x;
    float p1 = (w1 < 5.0f) ? pf.y : ps.y;
    float2 r;
    r.x = 1.41421356237f * p0 * u0;
    r.y = 1.41421356237f * p1 * u1;
    return r;
}

// scalar version (encoder-free; kept for reference parity) not needed.

// ======================= prep: transpose weights for constant bank =========
__global__ void prep_kernel(const float* __restrict__ d2w,
                            const float* __restrict__ mw,
                            const float* __restrict__ sw,
                            const float* __restrict__ d1w,
                            const float* __restrict__ e1w,
                            const float* __restrict__ d1b,
                            const float* __restrict__ d2b,
                            const float* __restrict__ e1b,
                            const float* __restrict__ mb,
                            const float* __restrict__ sb)
{
    int tid = blockIdx.x * 256 + threadIdx.x;
    int nt = gridDim.x * 256;
    // d2w [64][60] -> [h][o] 60x64
    for (int idx = tid; idx < 3840; idx += nt) {
        int h = idx >> 6, o = idx & 63;
        g_xpose[CW_D2 + idx] = d2w[o * 60 + h];
    }
    // mw, sw [32][60] -> [h][m] 60x32
    for (int idx = tid; idx < 1920; idx += nt) {
        int h = idx >> 5, m = idx & 31;
        g_xpose[CW_MW + idx] = mw[m * 60 + h];
        g_xpose[CW_SW + idx] = sw[m * 60 + h];
    }
    // d1w [60][32] -> [l][h] 32x60
    for (int idx = tid; idx < 1920; idx += nt) {
        int l = idx / 60, h = idx - l * 60;
        g_xpose[CW_D1 + idx] = d1w[h * 32 + l];
    }
    // e1w [60][64] -> [l][h] 64x60
    for (int idx = tid; idx < 3840; idx += nt) {
        int l = idx / 60, h = idx - l * 60;
        g_xpose[CW_E1 + idx] = e1w[h * 64 + l];
    }
    // biases
    if (tid < 60) g_xpose[CW_B1 + tid] = d1b[tid];
    if (tid < 64) g_xpose[CW_B2 + tid] = d2b[tid];
    if (tid < 60) g_xpose[CW_BE1 + tid] = e1b[tid];
    if (tid < 32) { g_xpose[CW_BM + tid] = mb[tid]; g_xpose[CW_BS + tid] = sb[tid]; }
}

// ======================= encoder =======================
// one thread per row n: x[64] -> h1[60] -> mu[32], logvar[32]
__global__ __launch_bounds__(256, 2) void enc_kernel(
    const float* __restrict__ x_in,
    float* __restrict__ out)
{
    int tid = threadIdx.x;
    int n = blockIdx.x * 256 + tid;

    unsigned long long h1a[30];
    {
        const ulonglong2* bb = (const ulonglong2*)&c_w[CW_BE1];
#pragma unroll
        for (int j = 0; j < 15; j++) {
            ulonglong2 bv = bb[j];
            h1a[2 * j] = bv.x;
            h1a[2 * j + 1] = bv.y;
        }
    }
    const float4* xr = (const float4*)(x_in + (size_t)n * 64);
#pragma unroll
    for (int q = 0; q < 16; q++) {
        float4 xv = xr[q];
        float xs[4] = {xv.x, xv.y, xv.z, xv.w};
#pragma unroll
        for (int s = 0; s < 4; s++) {
            unsigned long long xb = pk2(xs[s], xs[s]);
            const ulonglong2* wr =
                (const ulonglong2*)&c_w[CW_E1 + (q * 4 + s) * 60];
#pragma unroll
            for (int j = 0; j < 15; j++) {
                ulonglong2 wv = wr[j];
                h1a[2 * j]     = ffma2(wv.x, xb, h1a[2 * j]);
                h1a[2 * j + 1] = ffma2(wv.y, xb, h1a[2 * j + 1]);
            }
        }
    }
    float h1f[60];
#pragma unroll
    for (int j = 0; j < 30; j++) {
        float2 v = upk(h1a[j]);
        h1f[2 * j]     = fmaxf(v.x, 0.0f);
        h1f[2 * j + 1] = fmaxf(v.y, 0.0f);
    }

    float2* gm = (float2*)(g_musig + (size_t)n * 64);

    // ---- pass 1: mu ----
    {
        unsigned long long mua[16];
        const ulonglong2* bb = (const ulonglong2*)&c_w[CW_BM];
#pragma unroll
        for (int j = 0; j < 8; j++) {
            ulonglong2 bv = bb[j];
            mua[2 * j] = bv.x;
            mua[2 * j + 1] = bv.y;
        }
#pragma unroll
        for (int h = 0; h < 60; h++) {
            unsigned long long hb = pk2(h1f[h], h1f[h]);
            const ulonglong2* mr = (const ulonglong2*)&c_w[CW_MW + h * 32];
#pragma unroll
            for (int j = 0; j < 8; j++) {
                ulonglong2 mv = mr[j];
                mua[2 * j]     = ffma2(mv.x, hb, mua[2 * j]);
                mua[2 * j + 1] = ffma2(mv.y, hb, mua[2 * j + 1]);
            }
        }
        float2* mo = (float2*)(out + MU_OFF) + (size_t)n * 16;
#pragma unroll
        for (int j = 0; j < 16; j++) {
            float2 m = upk(mua[j]);
            mo[j] = m;
            gm[j] = m;
        }
    }

    // ---- pass 2: logvar ----
    {
        unsigned long long lva[16];
        const ulonglong2* bb = (const ulonglong2*)&c_w[CW_BS];
#pragma unroll
        for (int j = 0; j < 8; j++) {
            ulonglong2 bv = bb[j];
            lva[2 * j] = bv.x;
            lva[2 * j + 1] = bv.y;
        }
#pragma unroll
        for (int h = 0; h < 60; h++) {
            unsigned long long hb = pk2(h1f[h], h1f[h]);
            const ulonglong2* sr = (const ulonglong2*)&c_w[CW_SW + h * 32];
#pragma unroll
            for (int j = 0; j < 8; j++) {
                ulonglong2 sv = sr[j];
                lva[2 * j]     = ffma2(sv.x, hb, lva[2 * j]);
                lva[2 * j + 1] = ffma2(sv.y, hb, lva[2 * j + 1]);
            }
        }
        float2* vo = (float2*)(out + LV_OFF) + (size_t)n * 16;
#pragma unroll
        for (int j = 0; j < 16; j++) {
            float2 v = upk(lva[j]);
            vo[j] = v;
            gm[16 + j] = make_float2(expf(0.5f * v.x), expf(0.5f * v.y));
        }
    }
}

// ======================= decoder =======================
// one thread per (n, t). RNG pairs interleaved with dec1 accumulation;
// h3 parked in per-thread SMEM column (no barriers); dec2 single full pass.
// 128-reg budget for ILP (ptxas can pipeline sample chains + LDC prefetch).
__global__ __launch_bounds__(256, 2) void dec_kernel(float* __restrict__ out)
{
    extern __shared__ float h3s[];   // [60][256], per-thread column

    int tid = threadIdx.x;
    unsigned g = blockIdx.x * 256 + tid;
    int n = g & (NROWS - 1);
    int t = g >> 16;

    // ---- phase A: RNG (paired) -> z -> dec1 accumulate ----
    {
        unsigned long long h3a[30];
        const ulonglong2* bb = (const ulonglong2*)&c_w[CW_B1];
#pragma unroll
        for (int j = 0; j < 15; j++) {
            ulonglong2 bv = bb[j];
            h3a[2 * j] = bv.x;
            h3a[2 * j + 1] = bv.y;
        }

        uint32_t c0 = ((uint32_t)t << 21) | ((uint32_t)n << 5);
        const float4* m4 = (const float4*)(g_musig + (size_t)n * 64);
#pragma unroll
        for (int q = 0; q < 8; q++) {
            float4 mu = m4[q];
            float4 sd = m4[8 + q];
            float mus[4] = {mu.x, mu.y, mu.z, mu.w};
            float sds[4] = {sd.x, sd.y, sd.z, sd.w};
#pragma unroll
            for (int pr = 0; pr < 2; pr++) {
                int l = q * 4 + pr * 2;
                uint32_t b0 = tf_bits(c0 + (uint32_t)l);
                uint32_t b1 = tf_bits(c0 + (uint32_t)l + 1u);
                float2 ee = bits_pair_to_normal(b0, b1);
                float z0 = fmaf(ee.x, sds[2 * pr],     mus[2 * pr]);
                float z1 = fmaf(ee.y, sds[2 * pr + 1], mus[2 * pr + 1]);

                unsigned long long zb0 = pk2(z0, z0);
                const ulonglong2* wr0 = (const ulonglong2*)&c_w[CW_D1 + l * 60];
                unsigned long long zb1 = pk2(z1, z1);
                const ulonglong2* wr1 = (const ulonglong2*)&c_w[CW_D1 + (l + 1) * 60];
#pragma unroll
                for (int j = 0; j < 15; j++) {
                    ulonglong2 wv0 = wr0[j];
                    h3a[2 * j]     = ffma2(wv0.x, zb0, h3a[2 * j]);
                    h3a[2 * j + 1] = ffma2(wv0.y, zb0, h3a[2 * j + 1]);
                    ulonglong2 wv1 = wr1[j];
                    h3a[2 * j]     = ffma2(wv1.x, zb1, h3a[2 * j]);
                    h3a[2 * j + 1] = ffma2(wv1.y, zb1, h3a[2 * j + 1]);
                }
            }
        }
        // relu -> smem (own column; no cross-thread sharing, no barrier)
#pragma unroll
        for (int j = 0; j < 30; j++) {
            float2 v = upk(h3a[j]);
            h3s[(2 * j) * 256 + tid]     = fmaxf(v.x, 0.0f);
            h3s[(2 * j + 1) * 256 + tid] = fmaxf(v.y, 0.0f);
        }
    }

    // ---- phase B: o = dec2_w @ h3 + b, full 64-wide accumulate ----
    {
        unsigned long long oa[32];
        const ulonglong2* bb = (const ulonglong2*)&c_w[CW_B2];
#pragma unroll
        for (int j = 0; j < 16; j++) {
            ulonglong2 bv = bb[j];
            oa[2 * j] = bv.x;
            oa[2 * j + 1] = bv.y;
        }
#pragma unroll
        for (int h = 0; h < 60; h++) {
            float hv = h3s[h * 256 + tid];
            unsigned long long hb = pk2(hv, hv);
            const ulonglong2* wr = (const ulonglong2*)&c_w[CW_D2 + h * 64];
#pragma unroll
            for (int j = 0; j < 16; j++) {
                ulonglong2 wv = wr[j];
                oa[2 * j]     = ffma2(wv.x, hb, oa[2 * j]);
                oa[2 * j + 1] = ffma2(wv.y, hb, oa[2 * j + 1]);
            }
        }
        float* tb = out + (size_t)t * TRAJ_T_STRIDE + (size_t)n * 4;
#pragma unroll
        for (int hi = 0; hi < 16; hi++) {
            float2 a  = upk(oa[2 * hi]);
            float2 b2 = upk(oa[2 * hi + 1]);
            *(float4*)(tb + (size_t)hi * TRAJ_H_STRIDE) =
                make_float4(a.x, a.y, b2.x, b2.y);
        }
    }

    // prob_list: exp(pdf)==1.0f exactly in fp32, so 1/8.
    out[PROB_OFF + ((size_t)t << 16) + (size_t)n] = 0.125f;
}

extern "C" void kernel_launch(void* const* d_in, const int* in_sizes, int n_in,
                              void* d_out, int out_size) {
    (void)in_sizes; (void)n_in; (void)out_size;
    const float* h_input = (const float*)d_in[0];
    const float* e1w = (const float*)d_in[2];
    const float* e1b = (const float*)d_in[3];
    const float* mw  = (const float*)d_in[4];
    const float* mb  = (const float*)d_in[5];
    const float* sw  = (const float*)d_in[6];
    const float* sb  = (const float*)d_in[7];
    const float* d1w = (const float*)d_in[8];
    const float* d1b = (const float*)d_in[9];
    const float* d2w = (const float*)d_in[10];
    const float* d2b = (const float*)d_in[11];
    float* out = (float*)d_out;

    cudaFuncSetAttribute(dec_kernel,
                         cudaFuncAttributeMaxDynamicSharedMemorySize,
                         60 * 256 * 4);

    // transpose weights on device, then D2D into constant bank (capturable)
    prep_kernel<<<16, 256>>>(d2w, mw, sw, d1w, e1w, d1b, d2b, e1b, mb, sb);
    void* xp_ptr = nullptr;
    cudaGetSymbolAddress(&xp_ptr, g_xpose);
    cudaMemcpyToSymbolAsync(c_w, xp_ptr, 13696 * sizeof(float), 0,
                            cudaMemcpyDeviceToDevice, 0);

    enc_kernel<<<NROWS / 256, 256>>>(h_input, out);
    dec_kernel<<<(NROWS * TTRAJ) / 256, 256, 60 * 256 * 4>>>(out);
}